// round 17
// baseline (speedup 1.0000x reference)
#include <cuda_runtime.h>
#include <cuda_fp16.h>
#include <cstdint>
#include <math.h>

#define BATCH 2
#define SEQ   2048
#define DM    1024
#define NH    16
#define HW    64
#define SM_SCALE 0.125f   // 1/sqrt(64)
#define L2E   1.44269504f

#define NELEM (BATCH*NH*SEQ*HW)
#define XN    (BATCH*SEQ*DM)
#define WN    (DM*DM)

// Projected Q/K/V (single fp16 plane each) in [B, H, S, hw] layout.
__device__ __half g_qh[NELEM];
__device__ __half g_kh[NELEM];
__device__ __half g_vh[NELEM];
// fp16 planes of inputs X and weights W for the projections.
__device__ __half g_xh[3*XN];
__device__ __half g_wh[3*WN];

// ---------------------------------------------------------------------------
// Helpers
// ---------------------------------------------------------------------------
__device__ __forceinline__ uint32_t smem_u32(const void* p) {
    uint32_t a;
    asm("{ .reg .u64 t; cvta.to.shared.u64 t, %1; cvt.u32.u64 %0, t; }"
        : "=r"(a) : "l"(p));
    return a;
}

__device__ __forceinline__ void ldm4(uint32_t r[4], uint32_t addr) {
    asm volatile("ldmatrix.sync.aligned.m8n8.x4.shared.b16 {%0,%1,%2,%3}, [%4];"
                 : "=r"(r[0]), "=r"(r[1]), "=r"(r[2]), "=r"(r[3]) : "r"(addr));
}
__device__ __forceinline__ void ldm4t(uint32_t r[4], uint32_t addr) {
    asm volatile("ldmatrix.sync.aligned.m8n8.x4.trans.shared.b16 {%0,%1,%2,%3}, [%4];"
                 : "=r"(r[0]), "=r"(r[1]), "=r"(r[2]), "=r"(r[3]) : "r"(addr));
}

__device__ __forceinline__ void mma_f16(float acc[4], const uint32_t a[4],
                                        uint32_t b0, uint32_t b1) {
    asm volatile(
        "mma.sync.aligned.m16n8k16.row.col.f32.f16.f16.f32 "
        "{%0,%1,%2,%3}, {%4,%5,%6,%7}, {%8,%9}, {%0,%1,%2,%3};"
        : "+f"(acc[0]), "+f"(acc[1]), "+f"(acc[2]), "+f"(acc[3])
        : "r"(a[0]), "r"(a[1]), "r"(a[2]), "r"(a[3]), "r"(b0), "r"(b1));
}

__device__ __forceinline__ uint32_t packlo_h(float a, float b) {
    __half2 h = __floats2half2_rn(a, b);
    return *reinterpret_cast<uint32_t*>(&h);
}
// exp2 of a float pair on the f16x2 MUFU path; result = packed fp16 pair.
__device__ __forceinline__ uint32_t hexp2_pack(float a, float b) {
    __half2 h = h2exp2(__floats2half2_rn(a, b));
    return *reinterpret_cast<uint32_t*>(&h);
}

__device__ __forceinline__ void cpa16(uint32_t saddr, const void* g) {
    asm volatile("cp.async.cg.shared.global [%0], [%1], 16;"
                 :: "r"(saddr), "l"(g) : "memory");
}
#define CPA_COMMIT() asm volatile("cp.async.commit_group;" ::: "memory")
#define CPA_WAIT0()  asm volatile("cp.async.wait_group 0;" ::: "memory")

// ---------------------------------------------------------------------------
// Split inputs/weights into single fp16 planes (one bandwidth pass).
// ---------------------------------------------------------------------------
__global__ __launch_bounds__(256) void split_kernel(
    const float4* __restrict__ xq, const float4* __restrict__ xk,
    const float4* __restrict__ xv, const float4* __restrict__ wq,
    const float4* __restrict__ wk, const float4* __restrict__ wv)
{
    const int y = blockIdx.y;
    const float4* src;
    __half* dh;
    if (y < 3) {
        src = (y == 0) ? xq : (y == 1) ? xk : xv;
        dh = g_xh + (size_t)y * XN;
    } else {
        if (blockIdx.x >= 1024) return;
        int w = y - 3;
        src = (w == 0) ? wq : (w == 1) ? wk : wv;
        dh = g_wh + (size_t)w * WN;
    }
    size_t i = (size_t)blockIdx.x * 256 + threadIdx.x;
    float4 a = src[i];
    *(uint2*)(dh + i * 4) = make_uint2(packlo_h(a.x, a.y), packlo_h(a.z, a.w));
}

// ---------------------------------------------------------------------------
// Projection GEMM on mma.sync fp16, single pass.
// CTA 128x128, 4 warps (128 threads), warp tile 64x64 -> MMA:ldm4 = 4:1.
// K-chunk 32, 4 stages, TWO chunks per iteration, ONE barrier per pair.
// grid = (8, 32, 3), block = 128. smem 4 x 20480 = 81920 B, 2 CTAs/SM.
// ---------------------------------------------------------------------------
#define SROW   40
#define PA_TB  (128*SROW*2)
#define PB_TB  (128*SROW*2)
#define PSTG   (PA_TB + PB_TB)

__global__ __launch_bounds__(128, 2) void proj_mma()
{
    extern __shared__ unsigned short psm[];
    const uint32_t base = smem_u32(psm);

    const int z = blockIdx.z;
    const __half* Ah = g_xh + (size_t)z * XN;
    const __half* Bh = g_wh + (size_t)z * WN;
    __half* Oh = (z == 0) ? g_qh : (z == 1) ? g_kh : g_vh;

    const int tid   = threadIdx.x;
    const int wid   = tid >> 5;
    const int lane  = tid & 31;
    const int warpM = wid >> 1;      // 0..1 -> 64 rows
    const int warpN = wid & 1;       // 0..1 -> 64 cols
    const int m0    = blockIdx.y * 128;
    const int n0    = blockIdx.x * 128;

    const uint32_t aOff = ((uint32_t)(warpM * 64 + (lane & 15)) * SROW +
                           ((uint32_t)(lane >> 4) << 3)) * 2;
    const uint32_t bOff = ((uint32_t)(warpN * 64 + (lane & 7) + ((lane >> 4) << 3)) * SROW +
                           (((uint32_t)(lane >> 3) & 1) << 3)) * 2;

    float acc[4][8][4];
#pragma unroll
    for (int mf = 0; mf < 4; mf++)
#pragma unroll
        for (int nf = 0; nf < 8; nf++)
#pragma unroll
            for (int i = 0; i < 4; i++) acc[mf][nf][i] = 0.0f;

    auto load_chunk = [&](int c, int s) {
        const uint32_t bb = base + (uint32_t)s * PSTG;
        const int k0 = c * 32;
#pragma unroll
        for (int t = 0; t < 4; t++) {
            int i = tid + t * 128;           // 0..511
            int r = i >> 2, c8 = i & 3;
            uint32_t soff = (uint32_t)(r * SROW + c8 * 8) * 2;
            cpa16(bb + soff, Ah + (size_t)(m0 + r) * DM + k0 + c8 * 8);
            cpa16(bb + PA_TB + soff, Bh + (size_t)(n0 + r) * DM + k0 + c8 * 8);
        }
    };

    auto compute_chunk = [&](int s) {
        const uint32_t ah32 = base + (uint32_t)s * PSTG;
        const uint32_t bh32 = ah32 + PA_TB;
#pragma unroll
        for (int ks = 0; ks < 2; ks++) {
            const uint32_t kByte = (uint32_t)(ks * 32);
            uint32_t ah[4][4], bh[4][4];
#pragma unroll
            for (int mf = 0; mf < 4; mf++)
                ldm4(ah[mf], ah32 + aOff + (uint32_t)(mf * 16 * SROW * 2) + kByte);
#pragma unroll
            for (int pp = 0; pp < 4; pp++)
                ldm4(bh[pp], bh32 + bOff + (uint32_t)(pp * 16 * SROW * 2) + kByte);
#pragma unroll
            for (int mf = 0; mf < 4; mf++)
#pragma unroll
                for (int nf = 0; nf < 8; nf++) {
                    const int pp = nf >> 1, q = (nf & 1) * 2;
                    mma_f16(acc[mf][nf], ah[mf], bh[pp][q], bh[pp][q+1]);
                }
        }
    };

    load_chunk(0, 0);
    load_chunk(1, 1);
    CPA_COMMIT();

    for (int ip = 0; ip < 16; ip++) {
        CPA_WAIT0();
        __syncthreads();
        if (ip < 15) {
            load_chunk(2 * ip + 2, (2 * ip + 2) & 3);
            load_chunk(2 * ip + 3, (2 * ip + 3) & 3);
        }
        CPA_COMMIT();
        compute_chunk((2 * ip) & 3);
        compute_chunk((2 * ip + 1) & 3);
    }

    // Epilogue: single fp16 plane, [B, H, S, hw] layout.
    const int g  = lane >> 2;
    const int t2 = (lane & 3) << 1;
#pragma unroll
    for (int mf = 0; mf < 4; mf++) {
        int mA  = m0 + warpM * 64 + mf * 16 + g;
        int mB  = mA + 8;
        int bbA = mA >> 11, ssA = mA & (SEQ - 1);
        int bbB = mB >> 11, ssB = mB & (SEQ - 1);
#pragma unroll
        for (int nf = 0; nf < 8; nf++) {
            int n  = n0 + warpN * 64 + nf * 8 + t2;
            int hh = n >> 6, dd = n & 63;
            size_t offA = (((size_t)(bbA * NH + hh)) * SEQ + ssA) * HW + dd;
            size_t offB = (((size_t)(bbB * NH + hh)) * SEQ + ssB) * HW + dd;
            *(uint32_t*)(Oh + offA) = packlo_h(acc[mf][nf][0], acc[mf][nf][1]);
            *(uint32_t*)(Oh + offB) = packlo_h(acc[mf][nf][2], acc[mf][nf][3]);
        }
    }
}

// ---------------------------------------------------------------------------
// Flash attention, fp16 mma.sync. Q fragments hoisted to registers (loaded
// once); softmax exp on f16x2 MUFU; row sums via MMA-with-ones.
// K-tile 64 rows; 4 KV stages; one barrier per tile pair.
// smem = QTB + 8*KTB = 92160 B -> 2 CTAs/SM.
// ---------------------------------------------------------------------------
#define AROW 72
#define QTB  (128*AROW*2)
#define KTB  (64*AROW*2)
#define ONES_H2 0x3C003C00u   // fp16 {1.0, 1.0}

__device__ __forceinline__ void tile_async64(uint32_t sbase, const __half* g,
                                             int row0, int tid) {
#pragma unroll
    for (int t = 0; t < 2; t++) {
        int i  = tid + t * 256;
        int r  = i >> 3, c8 = i & 7;
        cpa16(sbase + (uint32_t)(r * AROW + c8 * 8) * 2,
              g + (size_t)(row0 + r) * HW + c8 * 8);
    }
}

__global__ __launch_bounds__(256, 2) void attn_mma(float* __restrict__ out)
{
    extern __shared__ unsigned short asm_[];
    const uint32_t base = smem_u32(asm_);
    const uint32_t qh32 = base;
    const uint32_t kvbase = base + QTB;

    const int bh = blockIdx.y;
    const int b  = bh >> 4;
    const int h  = bh & 15;
    const int qt = (int)gridDim.x - 1 - (int)blockIdx.x;
    const int q0 = qt * 128;

    const int tid  = threadIdx.x;
    const int warp = tid >> 5;
    const int lane = tid & 31;
    const int g    = lane >> 2;
    const int t2   = (lane & 3) << 1;

    const float SC2    = SM_SCALE * L2E;
    const float slope2 = exp2f(-0.5f * (float)(h + 1)) * L2E;

    const __half* Qh = g_qh + (size_t)bh * SEQ * HW;
    const __half* Kh = g_kh + (size_t)bh * SEQ * HW;
    const __half* Vh = g_vh + (size_t)bh * SEQ * HW;

#pragma unroll
    for (int t = 0; t < 4; t++) {
        int i = tid + t * 256;
        int r = i >> 3, c8 = i & 7;
        *(uint4*)((char*)asm_ + (uint32_t)(r * AROW + c8 * 8) * 2) =
            *(const uint4*)(Qh + (size_t)(q0 + r) * HW + c8 * 8);
    }

    const uint32_t aElem = (uint32_t)((warp * 16 + (lane & 15)) * AROW + ((lane >> 4) << 3));
    const uint32_t bElem = (uint32_t)(((lane & 7) + ((lane >> 4) << 3)) * AROW + (((lane >> 3) & 1) << 3));
    const uint32_t vElem = (uint32_t)((lane & 15) * AROW + ((lane >> 4) << 3));

    // Hoist Q fragments: read once, reuse for every K tile.
    __syncthreads();
    uint32_t qf[4][4];
#pragma unroll
    for (int ks = 0; ks < 4; ks++)
        ldm4(qf[ks], qh32 + (aElem + ks * 16) * 2);

    float oacc[8][4];
#pragma unroll
    for (int nf = 0; nf < 8; nf++)
#pragma unroll
        for (int e = 0; e < 4; e++) oacc[nf][e] = 0.0f;

    float m0r = -3e38f, m1r = -3e38f, l0 = 0.0f, l1 = 0.0f;
    const int row0 = q0 + warp * 16 + g;
    const int row1 = row0 + 8;

    auto do_tile = [&](int kt, int s, bool diag) {
        const uint32_t kh32 = kvbase + (uint32_t)(2 * s + 0) * KTB;
        const uint32_t vh32 = kvbase + (uint32_t)(2 * s + 1) * KTB;
        const int k0g = kt * 64;

        float sacc[8][4];
#pragma unroll
        for (int nf = 0; nf < 8; nf++)
#pragma unroll
            for (int e = 0; e < 4; e++) sacc[nf][e] = 0.0f;

#pragma unroll
        for (int ks = 0; ks < 4; ks++) {
#pragma unroll
            for (int pp = 0; pp < 4; pp++) {
                uint32_t bhx[4];
                uint32_t bd = (bElem + (uint32_t)(pp * 16 * AROW) + (uint32_t)(ks * 16)) * 2;
                ldm4(bhx, kh32 + bd);
                mma_f16(sacc[2*pp],   qf[ks], bhx[0], bhx[1]);
                mma_f16(sacc[2*pp+1], qf[ks], bhx[2], bhx[3]);
            }
        }

        float mx0 = -3e38f, mx1 = -3e38f;
#pragma unroll
        for (int nf = 0; nf < 8; nf++) {
            int c0 = k0g + nf * 8 + t2;
            int c1 = c0 + 1;
            float v0 = sacc[nf][0] * SC2 + slope2 * (float)(c0 - row0);
            float v1 = sacc[nf][1] * SC2 + slope2 * (float)(c1 - row0);
            float v2 = sacc[nf][2] * SC2 + slope2 * (float)(c0 - row1);
            float v3 = sacc[nf][3] * SC2 + slope2 * (float)(c1 - row1);
            if (diag) {
                if (c0 > row0) v0 = -3e38f;
                if (c1 > row0) v1 = -3e38f;
                if (c0 > row1) v2 = -3e38f;
                if (c1 > row1) v3 = -3e38f;
            }
            sacc[nf][0] = v0; sacc[nf][1] = v1; sacc[nf][2] = v2; sacc[nf][3] = v3;
            mx0 = fmaxf(mx0, fmaxf(v0, v1));
            mx1 = fmaxf(mx1, fmaxf(v2, v3));
        }
        mx0 = fmaxf(mx0, __shfl_xor_sync(0xffffffffu, mx0, 1));
        mx0 = fmaxf(mx0, __shfl_xor_sync(0xffffffffu, mx0, 2));
        mx1 = fmaxf(mx1, __shfl_xor_sync(0xffffffffu, mx1, 1));
        mx1 = fmaxf(mx1, __shfl_xor_sync(0xffffffffu, mx1, 2));

        float mn0 = fmaxf(m0r, mx0);
        float mn1 = fmaxf(m1r, mx1);
        float corr0 = exp2f(m0r - mn0);
        float corr1 = exp2f(m1r - mn1);
        m0r = mn0; m1r = mn1;

#pragma unroll
        for (int nf = 0; nf < 8; nf++) {
            oacc[nf][0] *= corr0; oacc[nf][1] *= corr0;
            oacc[nf][2] *= corr1; oacc[nf][3] *= corr1;
        }

        float lacc[4] = {0.f, 0.f, 0.f, 0.f};
#pragma unroll
        for (int ks = 0; ks < 4; ks++) {
            uint32_t pah[4];
            pah[0] = hexp2_pack(sacc[2*ks][0]   - mn0, sacc[2*ks][1]   - mn0);
            pah[1] = hexp2_pack(sacc[2*ks][2]   - mn1, sacc[2*ks][3]   - mn1);
            pah[2] = hexp2_pack(sacc[2*ks+1][0] - mn0, sacc[2*ks+1][1] - mn0);
            pah[3] = hexp2_pack(sacc[2*ks+1][2] - mn1, sacc[2*ks+1][3] - mn1);
            mma_f16(lacc, pah, ONES_H2, ONES_H2);
#pragma unroll
            for (int nb = 0; nb < 4; nb++) {
                uint32_t vhx[4];
                uint32_t vd = (vElem + (uint32_t)(ks * 16 * AROW) + (uint32_t)(nb * 16)) * 2;
                ldm4t(vhx, vh32 + vd);
                mma_f16(oacc[2*nb],   pah, vhx[0], vhx[1]);
                mma_f16(oacc[2*nb+1], pah, vhx[2], vhx[3]);
            }
        }
        l0 = l0 * corr0 + lacc[0];
        l1 = l1 * corr1 + lacc[2];
    };

    const int npairs = qt + 1;   // nkt = 2*qt+2 tiles, always even

    tile_async64(kvbase + 0 * KTB, Kh, 0, tid);
    tile_async64(kvbase + 1 * KTB, Vh, 0, tid);
    tile_async64(kvbase + 2 * KTB, Kh, 64, tid);
    tile_async64(kvbase + 3 * KTB, Vh, 64, tid);
    CPA_COMMIT();

    for (int ip = 0; ip < npairs; ip++) {
        CPA_WAIT0();
        __syncthreads();
        if (ip + 1 < npairs) {
            int t0 = 2 * ip + 2;
            int s0 = t0 & 3, s1 = (t0 + 1) & 3;
            tile_async64(kvbase + (uint32_t)(2 * s0 + 0) * KTB, Kh, t0 * 64, tid);
            tile_async64(kvbase + (uint32_t)(2 * s0 + 1) * KTB, Vh, t0 * 64, tid);
            tile_async64(kvbase + (uint32_t)(2 * s1 + 0) * KTB, Kh, (t0 + 1) * 64, tid);
            tile_async64(kvbase + (uint32_t)(2 * s1 + 1) * KTB, Vh, (t0 + 1) * 64, tid);
        }
        CPA_COMMIT();
        int kt0 = 2 * ip;
        do_tile(kt0,     kt0 & 3,       kt0     >= 2 * qt);
        do_tile(kt0 + 1, (kt0 + 1) & 3, kt0 + 1 >= 2 * qt);
    }

    // ---- epilogue: normalize + store to [B, S, D] ----
    const float inv0 = 1.0f / l0;
    const float inv1 = 1.0f / l1;
    float* op = out + (size_t)b * SEQ * DM + (size_t)h * HW;
#pragma unroll
    for (int nf = 0; nf < 8; nf++) {
        int col = nf * 8 + t2;
        *(float2*)(op + (size_t)row0 * DM + col) =
            make_float2(oacc[nf][0] * inv0, oacc[nf][1] * inv0);
        *(float2*)(op + (size_t)row1 * DM + col) =
            make_float2(oacc[nf][2] * inv1, oacc[nf][3] * inv1);
    }
}

// ---------------------------------------------------------------------------
// Launch: inputs order = queries, keys, values, mask, Wq, Wk, Wv.
// ---------------------------------------------------------------------------
extern "C" void kernel_launch(void* const* d_in, const int* in_sizes, int n_in,
                              void* d_out, int out_size)
{
    (void)in_sizes; (void)n_in; (void)out_size;
    const float4* q  = (const float4*)d_in[0];
    const float4* k  = (const float4*)d_in[1];
    const float4* v  = (const float4*)d_in[2];
    const float4* wq = (const float4*)d_in[4];
    const float4* wk = (const float4*)d_in[5];
    const float4* wv = (const float4*)d_in[6];
    float* out = (float*)d_out;

    const int proj_smem = 4 * PSTG;            // 81920 B
    cudaFuncSetAttribute(proj_mma, cudaFuncAttributeMaxDynamicSharedMemorySize, proj_smem);
    const int attn_smem = QTB + 8 * KTB;       // 92160 B
    cudaFuncSetAttribute(attn_mma, cudaFuncAttributeMaxDynamicSharedMemorySize, attn_smem);

    split_kernel<<<dim3(4096, 6), 256>>>(q, k, v, wq, wk, wv);
    proj_mma<<<dim3(DM/128, (BATCH*SEQ)/128, 3), 128, proj_smem>>>();
    attn_mma<<<dim3(SEQ/128, BATCH*NH), 256, attn_smem>>>(out);
}